// round 16
// baseline (speedup 1.0000x reference)
#include <cuda_runtime.h>
#include <cuda_bf16.h>
#include <math.h>

#define L_TOK  4680
#define DIM_   1536
#define NH     12
#define HD     128
#define FRAME  1560
#define WW     52
#define SINK   1
#define LOCAL  2
#define GK     1536

// Scratch (no cudaMalloc allowed)
__device__ float g_q[L_TOK * DIM_];
__device__ float g_k[L_TOK * DIM_];
__device__ float g_v[L_TOK * DIM_];
__device__ float g_a[L_TOK * DIM_];
__device__ __nv_bfloat16 g_act_hi[L_TOK * DIM_];
__device__ __nv_bfloat16 g_act_lo[L_TOK * DIM_];
__device__ __nv_bfloat16 g_wq_hi[DIM_ * DIM_];
__device__ __nv_bfloat16 g_wq_lo[DIM_ * DIM_];
__device__ __nv_bfloat16 g_wk_hi[DIM_ * DIM_];
__device__ __nv_bfloat16 g_wk_lo[DIM_ * DIM_];
__device__ __nv_bfloat16 g_wv_hi[DIM_ * DIM_];
__device__ __nv_bfloat16 g_wv_lo[DIM_ * DIM_];
__device__ __nv_bfloat16 g_wo_hi[DIM_ * DIM_];
__device__ __nv_bfloat16 g_wo_lo[DIM_ * DIM_];
__device__ __nv_bfloat16 g_qh[L_TOK * DIM_];
__device__ __nv_bfloat16 g_ql[L_TOK * DIM_];
__device__ __nv_bfloat16 g_kh[L_TOK * DIM_];
__device__ __nv_bfloat16 g_kl[L_TOK * DIM_];
__device__ __nv_bfloat16 g_vh[L_TOK * DIM_];
__device__ __nv_bfloat16 g_vl[L_TOK * DIM_];

// ---------------------------------------------------------------------------
// Split fp32 -> (hi, lo) bf16 planes.
// ---------------------------------------------------------------------------
__global__ void split_kernel(const float4* __restrict__ src,
                             __nv_bfloat162* __restrict__ hi,
                             __nv_bfloat162* __restrict__ lo,
                             int n4) {
    int i = blockIdx.x * blockDim.x + threadIdx.x;
    if (i >= n4) return;
    float4 f = src[i];
    __nv_bfloat16 h0 = __float2bfloat16_rn(f.x);
    __nv_bfloat16 h1 = __float2bfloat16_rn(f.y);
    __nv_bfloat16 h2 = __float2bfloat16_rn(f.z);
    __nv_bfloat16 h3 = __float2bfloat16_rn(f.w);
    __nv_bfloat16 l0 = __float2bfloat16_rn(f.x - __bfloat162float(h0));
    __nv_bfloat16 l1 = __float2bfloat16_rn(f.y - __bfloat162float(h1));
    __nv_bfloat16 l2 = __float2bfloat16_rn(f.z - __bfloat162float(h2));
    __nv_bfloat16 l3 = __float2bfloat16_rn(f.w - __bfloat162float(h3));
    hi[i * 2 + 0] = __halves2bfloat162(h0, h1);
    hi[i * 2 + 1] = __halves2bfloat162(h2, h3);
    lo[i * 2 + 0] = __halves2bfloat162(l0, l1);
    lo[i * 2 + 1] = __halves2bfloat162(l2, l3);
}

// ---------------------------------------------------------------------------
__device__ __forceinline__ void mma_bf16(float* c, const unsigned* a,
                                         unsigned b0, unsigned b1) {
    asm volatile(
        "mma.sync.aligned.m16n8k16.row.col.f32.bf16.bf16.f32 "
        "{%0,%1,%2,%3}, {%4,%5,%6,%7}, {%8,%9}, {%0,%1,%2,%3};"
        : "+f"(c[0]), "+f"(c[1]), "+f"(c[2]), "+f"(c[3])
        : "r"(a[0]), "r"(a[1]), "r"(a[2]), "r"(a[3]), "r"(b0), "r"(b1));
}

__device__ __forceinline__ void split2(float a, float b, unsigned& h, unsigned& l) {
    __nv_bfloat162 hv = __floats2bfloat162_rn(a, b);
    float2 hf = __bfloat1622float2(hv);
    __nv_bfloat162 lv = __floats2bfloat162_rn(a - hf.x, b - hf.y);
    h = *reinterpret_cast<unsigned*>(&hv);
    l = *reinterpret_cast<unsigned*>(&lv);
}

// ===========================================================================
// GEMM v4 "attention clone": C[M,N] = A @ B^T + bias, split-bf16 3-pass.
// Exact structural copy of the verified attention QK mainloop:
// 256 threads / 8 warps, warp tile 16 rows x 64 cols, pitch-136 smem,
// identical fragment addressing.  K consumed in 128-chunks (12 iters),
// accumulators persist across chunks.  Block tile 128 x 64.
// ===========================================================================
#define GP 136   // smem pitch in bf16 (same family as attention QP)

__global__ __launch_bounds__(256)
void gemm_v4(const __nv_bfloat16* __restrict__ Ah,
             const __nv_bfloat16* __restrict__ Al,
             const __nv_bfloat16* __restrict__ Bh,
             const __nv_bfloat16* __restrict__ Bl,
             const float* __restrict__ bias,
             float* __restrict__ C, int M) {
    extern __shared__ __nv_bfloat16 smg[];
    __nv_bfloat16* sAh = smg;                 // [128][GP]
    __nv_bfloat16* sAl = sAh + 128 * GP;
    __nv_bfloat16* sBh = sAl + 128 * GP;      // [64][GP]
    __nv_bfloat16* sBl = sBh + 64 * GP;

    const int tid = threadIdx.x;
    const int lane = tid & 31, wid = tid >> 5;
    const int g = lane >> 2, tq2 = (lane & 3) * 2;
    const int m0 = blockIdx.y * 128, n0 = blockIdx.x * 64;
    const int r0 = wid * 16;

    float acc[8][4];
#pragma unroll
    for (int i = 0; i < 8; i++)
#pragma unroll
        for (int j = 0; j < 4; j++) acc[i][j] = 0.f;

    for (int kc0 = 0; kc0 < GK / 128; kc0++) {   // 12 chunks
        const int k0 = kc0 * 128;
        __syncthreads();
        // A chunk 128x128, both planes (rows clamped at M boundary)
#pragma unroll
        for (int it = 0; it < 8; it++) {
            int idx = it * 256 + tid;
            int row = idx >> 4, ch = (idx & 15) * 8;
            int ar = m0 + row;
            ar = ar < M ? ar : (M - 1);
            size_t off = (size_t)ar * GK + k0 + ch;
            *(uint4*)(sAh + row * GP + ch) = *(const uint4*)(Ah + off);
            *(uint4*)(sAl + row * GP + ch) = *(const uint4*)(Al + off);
        }
        // B chunk 64x128, both planes
#pragma unroll
        for (int it = 0; it < 4; it++) {
            int idx = it * 256 + tid;
            int row = idx >> 4, ch = (idx & 15) * 8;
            size_t off = (size_t)(n0 + row) * GK + k0 + ch;
            *(uint4*)(sBh + row * GP + ch) = *(const uint4*)(Bh + off);
            *(uint4*)(sBl + row * GP + ch) = *(const uint4*)(Bl + off);
        }
        __syncthreads();

        // --- exact attention QK fragment pattern ---
#pragma unroll
        for (int kc = 0; kc < 8; kc++) {
            const int kb = kc * 16 + tq2;
            unsigned qh[4], ql[4];
            qh[0] = *(const unsigned*)(sAh + (r0 + g) * GP + kb);
            qh[1] = *(const unsigned*)(sAh + (r0 + g + 8) * GP + kb);
            qh[2] = *(const unsigned*)(sAh + (r0 + g) * GP + kb + 8);
            qh[3] = *(const unsigned*)(sAh + (r0 + g + 8) * GP + kb + 8);
            ql[0] = *(const unsigned*)(sAl + (r0 + g) * GP + kb);
            ql[1] = *(const unsigned*)(sAl + (r0 + g + 8) * GP + kb);
            ql[2] = *(const unsigned*)(sAl + (r0 + g) * GP + kb + 8);
            ql[3] = *(const unsigned*)(sAl + (r0 + g + 8) * GP + kb + 8);
#pragma unroll
            for (int nt = 0; nt < 8; nt++) {
                const int kr = nt * 8 + g;
                unsigned kh0 = *(const unsigned*)(sBh + kr * GP + kb);
                unsigned kh1 = *(const unsigned*)(sBh + kr * GP + kb + 8);
                unsigned kl0 = *(const unsigned*)(sBl + kr * GP + kb);
                unsigned kl1 = *(const unsigned*)(sBl + kr * GP + kb + 8);
                mma_bf16(acc[nt], qh, kh0, kh1);
                mma_bf16(acc[nt], ql, kh0, kh1);
                mma_bf16(acc[nt], qh, kl0, kl1);
            }
        }
    }

    // epilogue (same C-fragment mapping as attention epilogue)
    const int row0 = m0 + r0 + g, row1 = row0 + 8;
#pragma unroll
    for (int nt = 0; nt < 8; nt++) {
        int col = n0 + nt * 8 + tq2;
        float b0 = bias[col], b1 = bias[col + 1];
        if (row0 < M) {
            float2 v = make_float2(acc[nt][0] + b0, acc[nt][1] + b1);
            *(float2*)(C + (size_t)row0 * GK + col) = v;
        }
        if (row1 < M) {
            float2 v = make_float2(acc[nt][2] + b0, acc[nt][3] + b1);
            *(float2*)(C + (size_t)row1 * GK + col) = v;
        }
    }
}

// ---------------------------------------------------------------------------
// In-place RMSNorm + 3D RoPE.  One block per token.  (verified; unchanged)
// ---------------------------------------------------------------------------
__global__ void norm_rope_kernel(float* __restrict__ data,
                                 const float* __restrict__ g,
                                 const float* __restrict__ freqs) {
    const int t = blockIdx.x;
    const int tid = threadIdx.x;
    float* row = data + (size_t)t * DIM_;

    float ss = 0.f;
    for (int c = tid; c < DIM_; c += 256) { float v = row[c]; ss += v * v; }
#pragma unroll
    for (int o = 16; o; o >>= 1) ss += __shfl_xor_sync(0xffffffffu, ss, o);

    __shared__ float red[8];
    __shared__ float inv_s;
    if ((tid & 31) == 0) red[tid >> 5] = ss;
    __syncthreads();
    if (tid == 0) {
        float tot = 0.f;
#pragma unroll
        for (int i = 0; i < 8; i++) tot += red[i];
        inv_s = rsqrtf(tot / (float)DIM_ + 1e-6f);
    }
    __syncthreads();
    const float inv = inv_s;

    const int f = t / FRAME, rem = t % FRAME;
    const int hh = rem / WW, ww = rem % WW;

    for (int p = tid; p < DIM_ / 2; p += 256) {
        int pin = p & 63;
        int pos = (pin < 22) ? f : ((pin < 43) ? hh : ww);
        float cs = freqs[(pos * 64 + pin) * 2 + 0];
        float sn = freqs[(pos * 64 + pin) * 2 + 1];
        int c = p * 2;
        float a = row[c]     * inv * g[c];
        float b = row[c + 1] * inv * g[c + 1];
        row[c]     = a * cs - b * sn;
        row[c + 1] = a * sn + b * cs;
    }
}

// ---------------------------------------------------------------------------
// Tensor-core flash attention, split-bf16 3-pass.  (verified R4; unchanged)
// ---------------------------------------------------------------------------
#define QP 136
#define VP 72

__global__ __launch_bounds__(256, 1)
void attn_mma_kernel(const __nv_bfloat16* __restrict__ Qh,
                     const __nv_bfloat16* __restrict__ Ql,
                     const __nv_bfloat16* __restrict__ Kh,
                     const __nv_bfloat16* __restrict__ Kl,
                     const __nv_bfloat16* __restrict__ Vh,
                     const __nv_bfloat16* __restrict__ Vl,
                     float* __restrict__ O) {
    extern __shared__ __nv_bfloat16 smb[];
    __nv_bfloat16* sQh = smb;
    __nv_bfloat16* sQl = sQh + 128 * QP;
    __nv_bfloat16* sKh = sQl + 128 * QP;
    __nv_bfloat16* sKl = sKh + 64 * QP;
    __nv_bfloat16* sVh = sKl + 64 * QP;
    __nv_bfloat16* sVl = sVh + 128 * VP;

    const int tid = threadIdx.x;
    const int lane = tid & 31, wid = tid >> 5;
    const int g = lane >> 2, tq2 = (lane & 3) * 2;
    const int h = blockIdx.y;
    const int q0 = blockIdx.x * 128;
    const int r0 = wid * 16;
    const float scale = 0.08838834764831845f;

#pragma unroll
    for (int it = 0; it < 8; it++) {
        int idx = it * 256 + tid;
        int row = idx >> 4, ch = (idx & 15) * 8;
        uint4 zh = make_uint4(0, 0, 0, 0), zl = zh;
        if (q0 + row < L_TOK) {
            size_t off = (size_t)(q0 + row) * DIM_ + h * HD + ch;
            zh = *(const uint4*)(Qh + off);
            zl = *(const uint4*)(Ql + off);
        }
        *(uint4*)(sQh + row * QP + ch) = zh;
        *(uint4*)(sQl + row * QP + ch) = zl;
    }

    float m_pr0 = -INFINITY, m_pr1 = -INFINITY;
    float l0 = 0.f, l1 = 0.f;
    float oacc[16][4];
#pragma unroll
    for (int i = 0; i < 16; i++)
#pragma unroll
        for (int j = 0; j < 4; j++) oacc[i][j] = 0.f;

    const int row_g0 = q0 + r0 + g, row_g1 = row_g0 + 8;
    const int qf0 = min(row_g0, L_TOK - 1) / FRAME;
    const int qf1 = min(row_g1, L_TOK - 1) / FRAME;

    const int qmax = min(q0 + 127, L_TOK - 1);
    const int kend = min(L_TOK, (qmax / FRAME + 1) * FRAME);
    const int ntiles = (kend + 63) >> 6;

    for (int t = 0; t < ntiles; t++) {
        const int k0 = t * 64;
        __syncthreads();
#pragma unroll
        for (int it = 0; it < 4; it++) {
            int idx = it * 256 + tid;
            int row = idx >> 4, ch = (idx & 15) * 8;
            uint4 zh = make_uint4(0, 0, 0, 0), zl = zh;
            if (k0 + row < L_TOK) {
                size_t off = (size_t)(k0 + row) * DIM_ + h * HD + ch;
                zh = *(const uint4*)(Kh + off);
                zl = *(const uint4*)(Kl + off);
            }
            *(uint4*)(sKh + row * QP + ch) = zh;
            *(uint4*)(sKl + row * QP + ch) = zl;
        }
#pragma unroll
        for (int it = 0; it < 4; it++) {
            int idx = it * 256 + tid;
            int key = idx & 63, dc = (idx >> 6) * 8;
            uint4 zh = make_uint4(0, 0, 0, 0), zl = zh;
            if (k0 + key < L_TOK) {
                size_t off = (size_t)(k0 + key) * DIM_ + h * HD + dc;
                zh = *(const uint4*)(Vh + off);
                zl = *(const uint4*)(Vl + off);
            }
            const __nv_bfloat16* eh = reinterpret_cast<const __nv_bfloat16*>(&zh);
            const __nv_bfloat16* el = reinterpret_cast<const __nv_bfloat16*>(&zl);
#pragma unroll
            for (int e = 0; e < 8; e++) {
                sVh[(dc + e) * VP + key] = eh[e];
                sVl[(dc + e) * VP + key] = el[e];
            }
        }
        __syncthreads();

        float sacc[8][4];
#pragma unroll
        for (int i = 0; i < 8; i++)
#pragma unroll
            for (int j = 0; j < 4; j++) sacc[i][j] = 0.f;

#pragma unroll
        for (int kc = 0; kc < 8; kc++) {
            const int kb = kc * 16 + tq2;
            unsigned qh[4], ql[4];
            qh[0] = *(const unsigned*)(sQh + (r0 + g) * QP + kb);
            qh[1] = *(const unsigned*)(sQh + (r0 + g + 8) * QP + kb);
            qh[2] = *(const unsigned*)(sQh + (r0 + g) * QP + kb + 8);
            qh[3] = *(const unsigned*)(sQh + (r0 + g + 8) * QP + kb + 8);
            ql[0] = *(const unsigned*)(sQl + (r0 + g) * QP + kb);
            ql[1] = *(const unsigned*)(sQl + (r0 + g + 8) * QP + kb);
            ql[2] = *(const unsigned*)(sQl + (r0 + g) * QP + kb + 8);
            ql[3] = *(const unsigned*)(sQl + (r0 + g + 8) * QP + kb + 8);
#pragma unroll
            for (int nt = 0; nt < 8; nt++) {
                const int kr = nt * 8 + g;
                unsigned kh0 = *(const unsigned*)(sKh + kr * QP + kb);
                unsigned kh1 = *(const unsigned*)(sKh + kr * QP + kb + 8);
                unsigned kl0 = *(const unsigned*)(sKl + kr * QP + kb);
                unsigned kl1 = *(const unsigned*)(sKl + kr * QP + kb + 8);
                mma_bf16(sacc[nt], qh, kh0, kh1);
                mma_bf16(sacc[nt], ql, kh0, kh1);
                mma_bf16(sacc[nt], qh, kl0, kl1);
            }
        }

        float mloc0 = -INFINITY, mloc1 = -INFINITY;
#pragma unroll
        for (int nt = 0; nt < 8; nt++) {
            int c0 = k0 + nt * 8 + tq2, c1 = c0 + 1;
            int kf0 = c0 / FRAME, kf1 = c1 / FRAME;
            bool a00 = (c0 < L_TOK) && kf0 <= qf0 && (kf0 < SINK || qf0 - kf0 < LOCAL);
            bool a10 = (c1 < L_TOK) && kf1 <= qf0 && (kf1 < SINK || qf0 - kf1 < LOCAL);
            bool a01 = (c0 < L_TOK) && kf0 <= qf1 && (kf0 < SINK || qf1 - kf0 < LOCAL);
            bool a11 = (c1 < L_TOK) && kf1 <= qf1 && (kf1 < SINK || qf1 - kf1 < LOCAL);
            sacc[nt][0] = a00 ? sacc[nt][0] * scale : -INFINITY;
            sacc[nt][1] = a10 ? sacc[nt][1] * scale : -INFINITY;
            sacc[nt][2] = a01 ? sacc[nt][2] * scale : -INFINITY;
            sacc[nt][3] = a11 ? sacc[nt][3] * scale : -INFINITY;
            mloc0 = fmaxf(mloc0, fmaxf(sacc[nt][0], sacc[nt][1]));
            mloc1 = fmaxf(mloc1, fmaxf(sacc[nt][2], sacc[nt][3]));
        }
        mloc0 = fmaxf(mloc0, __shfl_xor_sync(0xffffffffu, mloc0, 1));
        mloc0 = fmaxf(mloc0, __shfl_xor_sync(0xffffffffu, mloc0, 2));
        mloc1 = fmaxf(mloc1, __shfl_xor_sync(0xffffffffu, mloc1, 1));
        mloc1 = fmaxf(mloc1, __shfl_xor_sync(0xffffffffu, mloc1, 2));

        float mn0 = fmaxf(m_pr0, mloc0), mn1 = fmaxf(m_pr1, mloc1);
        float alpha0 = __expf(m_pr0 - mn0), alpha1 = __expf(m_pr1 - mn1);
        m_pr0 = mn0; m_pr1 = mn1;

        float rs0 = 0.f, rs1 = 0.f;
#pragma unroll
        for (int nt = 0; nt < 8; nt++) {
            sacc[nt][0] = __expf(sacc[nt][0] - mn0);
            sacc[nt][1] = __expf(sacc[nt][1] - mn0);
            sacc[nt][2] = __expf(sacc[nt][2] - mn1);
            sacc[nt][3] = __expf(sacc[nt][3] - mn1);
            rs0 += sacc[nt][0] + sacc[nt][1];
            rs1 += sacc[nt][2] + sacc[nt][3];
        }
        rs0 += __shfl_xor_sync(0xffffffffu, rs0, 1);
        rs0 += __shfl_xor_sync(0xffffffffu, rs0, 2);
        rs1 += __shfl_xor_sync(0xffffffffu, rs1, 1);
        rs1 += __shfl_xor_sync(0xffffffffu, rs1, 2);
        l0 = l0 * alpha0 + rs0;
        l1 = l1 * alpha1 + rs1;

#pragma unroll
        for (int dt = 0; dt < 16; dt++) {
            oacc[dt][0] *= alpha0; oacc[dt][1] *= alpha0;
            oacc[dt][2] *= alpha1; oacc[dt][3] *= alpha1;
        }

#pragma unroll
        for (int kc2 = 0; kc2 < 4; kc2++) {
            unsigned pah[4], pal[4];
            split2(sacc[2 * kc2][0],     sacc[2 * kc2][1],     pah[0], pal[0]);
            split2(sacc[2 * kc2][2],     sacc[2 * kc2][3],     pah[1], pal[1]);
            split2(sacc[2 * kc2 + 1][0], sacc[2 * kc2 + 1][1], pah[2], pal[2]);
            split2(sacc[2 * kc2 + 1][2], sacc[2 * kc2 + 1][3], pah[3], pal[3]);
            const int kb2 = kc2 * 16 + tq2;
#pragma unroll
            for (int dt = 0; dt < 16; dt++) {
                const int vr = dt * 8 + g;
                unsigned vh0 = *(const unsigned*)(sVh + vr * VP + kb2);
                unsigned vh1 = *(const unsigned*)(sVh + vr * VP + kb2 + 8);
                unsigned vl0 = *(const unsigned*)(sVl + vr * VP + kb2);
                unsigned vl1 = *(const unsigned*)(sVl + vr * VP + kb2 + 8);
                mma_bf16(oacc[dt], pah, vh0, vh1);
                mma_bf16(oacc[dt], pal, vh0, vh1);
                mma_bf16(oacc[dt], pah, vl0, vl1);
            }
        }
    }

    const float li0 = 1.f / l0, li1 = 1.f / l1;
#pragma unroll
    for (int dt = 0; dt < 16; dt++) {
        const int d = dt * 8 + tq2;
        if (row_g0 < L_TOK) {
            float2 v = make_float2(oacc[dt][0] * li0, oacc[dt][1] * li0);
            *(float2*)(O + (size_t)row_g0 * DIM_ + h * HD + d) = v;
        }
        if (row_g1 < L_TOK) {
            float2 v = make_float2(oacc[dt][2] * li1, oacc[dt][3] * li1);
            *(float2*)(O + (size_t)row_g1 * DIM_ + h * HD + d) = v;
        }
    }
}

// ---------------------------------------------------------------------------
extern "C" void kernel_launch(void* const* d_in, const int* in_sizes, int n_in,
                              void* d_out, int out_size) {
    const float* x  = (const float*)d_in[0];
    const float* wq = (const float*)d_in[1];
    const float* bq = (const float*)d_in[2];
    const float* wk = (const float*)d_in[3];
    const float* bk = (const float*)d_in[4];
    const float* wv = (const float*)d_in[5];
    const float* bv = (const float*)d_in[6];
    const float* wo = (const float*)d_in[7];
    const float* bo = (const float*)d_in[8];
    const float* gq = (const float*)d_in[9];
    const float* gk = (const float*)d_in[10];
    const float* fr = (const float*)d_in[11];
    float* out = (float*)d_out;

    float *q, *k, *v, *a;
    __nv_bfloat16 *ah, *al, *qwh, *qwl, *kwh, *kwl, *vwh, *vwl, *owh, *owl;
    __nv_bfloat16 *qh, *ql, *kh, *kl, *vh, *vl;
    cudaGetSymbolAddress((void**)&q, g_q);
    cudaGetSymbolAddress((void**)&k, g_k);
    cudaGetSymbolAddress((void**)&v, g_v);
    cudaGetSymbolAddress((void**)&a, g_a);
    cudaGetSymbolAddress((void**)&ah, g_act_hi);
    cudaGetSymbolAddress((void**)&al, g_act_lo);
    cudaGetSymbolAddress((void**)&qwh, g_wq_hi);
    cudaGetSymbolAddress((void**)&qwl, g_wq_lo);
    cudaGetSymbolAddress((void**)&kwh, g_wk_hi);
    cudaGetSymbolAddress((void**)&kwl, g_wk_lo);
    cudaGetSymbolAddress((void**)&vwh, g_wv_hi);
    cudaGetSymbolAddress((void**)&vwl, g_wv_lo);
    cudaGetSymbolAddress((void**)&owh, g_wo_hi);
    cudaGetSymbolAddress((void**)&owl, g_wo_lo);
    cudaGetSymbolAddress((void**)&qh, g_qh);
    cudaGetSymbolAddress((void**)&ql, g_ql);
    cudaGetSymbolAddress((void**)&kh, g_kh);
    cudaGetSymbolAddress((void**)&kl, g_kl);
    cudaGetSymbolAddress((void**)&vh, g_vh);
    cudaGetSymbolAddress((void**)&vl, g_vl);

    const int nact4 = L_TOK * DIM_ / 4;
    const int nw4 = DIM_ * DIM_ / 4;
    const int SB = 256;
    dim3 gact((nact4 + SB - 1) / SB), gw((nw4 + SB - 1) / SB);
    dim3 gg(DIM_ / 64, (L_TOK + 127) / 128);   // (24, 37)

    const int gsmem = (2 * 128 + 2 * 64) * GP * (int)sizeof(__nv_bfloat16);
    cudaFuncSetAttribute(gemm_v4,
                         cudaFuncAttributeMaxDynamicSharedMemorySize, gsmem);

    // Interleaved so GEMMs land at launch slots 2/4/6 for the ncu capture.
    split_kernel<<<gact, SB>>>((const float4*)x, (__nv_bfloat162*)ah,
                               (__nv_bfloat162*)al, nact4);          // 0
    split_kernel<<<gw, SB>>>((const float4*)wq, (__nv_bfloat162*)qwh,
                             (__nv_bfloat162*)qwl, nw4);             // 1
    gemm_v4<<<gg, 256, gsmem>>>(ah, al, qwh, qwl, bq, q, L_TOK);     // 2
    split_kernel<<<gw, SB>>>((const float4*)wk, (__nv_bfloat162*)kwh,
                             (__nv_bfloat162*)kwl, nw4);             // 3
    gemm_v4<<<gg, 256, gsmem>>>(ah, al, kwh, kwl, bk, k, L_TOK);     // 4
    split_kernel<<<gw, SB>>>((const float4*)wv, (__nv_bfloat162*)vwh,
                             (__nv_bfloat162*)vwl, nw4);             // 5
    gemm_v4<<<gg, 256, gsmem>>>(ah, al, vwh, vwl, bv, v, L_TOK);     // 6

    norm_rope_kernel<<<L_TOK, 256>>>(q, gq, fr);
    norm_rope_kernel<<<L_TOK, 256>>>(k, gk, fr);

    split_kernel<<<gact, SB>>>((const float4*)q, (__nv_bfloat162*)qh,
                               (__nv_bfloat162*)ql, nact4);
    split_kernel<<<gact, SB>>>((const float4*)k, (__nv_bfloat162*)kh,
                               (__nv_bfloat162*)kl, nact4);
    split_kernel<<<gact, SB>>>((const float4*)v, (__nv_bfloat162*)vh,
                               (__nv_bfloat162*)vl, nact4);

    size_t asmem = (size_t)(2 * 128 * QP + 2 * 64 * QP + 2 * 128 * VP) *
                   sizeof(__nv_bfloat16);
    cudaFuncSetAttribute(attn_mma_kernel,
                         cudaFuncAttributeMaxDynamicSharedMemorySize, (int)asmem);
    attn_mma_kernel<<<dim3((L_TOK + 127) / 128, NH), 256, asmem>>>(
        qh, ql, kh, kl, vh, vl, a);

    split_kernel<<<gact, SB>>>((const float4*)a, (__nv_bfloat162*)ah,
                               (__nv_bfloat162*)al, nact4);
    split_kernel<<<gw, SB>>>((const float4*)wo, (__nv_bfloat162*)owh,
                             (__nv_bfloat162*)owl, nw4);
    gemm_v4<<<gg, 256, gsmem>>>(ah, al, owh, owl, bo, out, L_TOK);
}

// round 17
// speedup vs baseline: 1.0877x; 1.0877x over previous
#include <cuda_runtime.h>
#include <cuda_bf16.h>
#include <math.h>

#define L_TOK  4680
#define DIM_   1536
#define NH     12
#define HD     128
#define FRAME  1560
#define WW     52
#define SINK   1
#define LOCAL  2
#define GK     1536

// Scratch (no cudaMalloc allowed)
__device__ float g_q[L_TOK * DIM_];
__device__ float g_k[L_TOK * DIM_];
__device__ __nv_bfloat16 g_act_hi[L_TOK * DIM_];
__device__ __nv_bfloat16 g_act_lo[L_TOK * DIM_];
__device__ __nv_bfloat16 g_wq_hi[DIM_ * DIM_];
__device__ __nv_bfloat16 g_wq_lo[DIM_ * DIM_];
__device__ __nv_bfloat16 g_wk_hi[DIM_ * DIM_];
__device__ __nv_bfloat16 g_wk_lo[DIM_ * DIM_];
__device__ __nv_bfloat16 g_wv_hi[DIM_ * DIM_];
__device__ __nv_bfloat16 g_wv_lo[DIM_ * DIM_];
__device__ __nv_bfloat16 g_wo_hi[DIM_ * DIM_];
__device__ __nv_bfloat16 g_wo_lo[DIM_ * DIM_];
__device__ __nv_bfloat16 g_qh[L_TOK * DIM_];
__device__ __nv_bfloat16 g_ql[L_TOK * DIM_];
__device__ __nv_bfloat16 g_kh[L_TOK * DIM_];
__device__ __nv_bfloat16 g_kl[L_TOK * DIM_];
__device__ __nv_bfloat16 g_vh[L_TOK * DIM_];
__device__ __nv_bfloat16 g_vl[L_TOK * DIM_];

// ---------------------------------------------------------------------------
__device__ __forceinline__ void mma_bf16(float* c, const unsigned* a,
                                         unsigned b0, unsigned b1) {
    asm volatile(
        "mma.sync.aligned.m16n8k16.row.col.f32.bf16.bf16.f32 "
        "{%0,%1,%2,%3}, {%4,%5,%6,%7}, {%8,%9}, {%0,%1,%2,%3};"
        : "+f"(c[0]), "+f"(c[1]), "+f"(c[2]), "+f"(c[3])
        : "r"(a[0]), "r"(a[1]), "r"(a[2]), "r"(a[3]), "r"(b0), "r"(b1));
}

__device__ __forceinline__ void split2(float a, float b, unsigned& h, unsigned& l) {
    __nv_bfloat162 hv = __floats2bfloat162_rn(a, b);
    float2 hf = __bfloat1622float2(hv);
    __nv_bfloat162 lv = __floats2bfloat162_rn(a - hf.x, b - hf.y);
    h = *reinterpret_cast<unsigned*>(&hv);
    l = *reinterpret_cast<unsigned*>(&lv);
}

__device__ __forceinline__ void cp16(void* s, const void* g, bool valid) {
    unsigned sa = (unsigned)__cvta_generic_to_shared(s);
    int sz = valid ? 16 : 0;
    asm volatile("cp.async.ca.shared.global [%0], [%1], 16, %2;"
                 :: "r"(sa), "l"(g), "r"(sz));
}

// ---------------------------------------------------------------------------
// Split fp32 -> (hi, lo) bf16 planes.  (for x and the 4 weights)
// ---------------------------------------------------------------------------
__global__ void split_kernel(const float4* __restrict__ src,
                             __nv_bfloat162* __restrict__ hi,
                             __nv_bfloat162* __restrict__ lo,
                             int n4) {
    int i = blockIdx.x * blockDim.x + threadIdx.x;
    if (i >= n4) return;
    float4 f = src[i];
    unsigned h0, l0, h1, l1;
    split2(f.x, f.y, h0, l0);
    split2(f.z, f.w, h1, l1);
    hi[i * 2 + 0] = *reinterpret_cast<__nv_bfloat162*>(&h0);
    hi[i * 2 + 1] = *reinterpret_cast<__nv_bfloat162*>(&h1);
    lo[i * 2 + 0] = *reinterpret_cast<__nv_bfloat162*>(&l0);
    lo[i * 2 + 1] = *reinterpret_cast<__nv_bfloat162*>(&l1);
}

// ---------------------------------------------------------------------------
// GEMM v2 (verified R5, 2258us config): C = A @ B^T + bias, split-bf16 3-pass.
// 128 threads (4 warps 2x2), block 128x128, warp 64x64, BK=32, cp.async
// double-buffered.  SPLIT_OUT=true writes bf16 hi/lo planes instead of fp32.
// ---------------------------------------------------------------------------
#define SPITCH 40
#define GTILE (128 * SPITCH)

template <bool SPLIT_OUT>
__global__ __launch_bounds__(128, 2)
void gemm_bf16s_v2(const __nv_bfloat16* __restrict__ Ah,
                   const __nv_bfloat16* __restrict__ Al,
                   const __nv_bfloat16* __restrict__ Bh,
                   const __nv_bfloat16* __restrict__ Bl,
                   const float* __restrict__ bias,
                   float* __restrict__ C,
                   __nv_bfloat16* __restrict__ Ch,
                   __nv_bfloat16* __restrict__ Cl,
                   int M) {
    extern __shared__ __nv_bfloat16 smg[];
    const int tid = threadIdx.x;
    const int lane = tid & 31, wid = tid >> 5;
    const int wm = (wid & 1) * 64, wn = (wid >> 1) * 64;
    const int m0 = blockIdx.y * 128, n0 = blockIdx.x * 128;
    const int quad = lane >> 2, tq = (lane & 3) * 2;

    float acc[4][8][4];
#pragma unroll
    for (int i = 0; i < 4; i++)
#pragma unroll
        for (int j = 0; j < 8; j++)
#pragma unroll
            for (int r = 0; r < 4; r++) acc[i][j][r] = 0.f;

    const int NK = GK / 32;  // 48

#define ISSUE_TILE(kt, buf)                                                   \
    {                                                                         \
        const int k0i = (kt) * 32;                                            \
        __nv_bfloat16* dAh = smg + ((buf) * 4 + 0) * GTILE;                   \
        __nv_bfloat16* dAl = smg + ((buf) * 4 + 1) * GTILE;                   \
        __nv_bfloat16* dBh = smg + ((buf) * 4 + 2) * GTILE;                   \
        __nv_bfloat16* dBl = smg + ((buf) * 4 + 3) * GTILE;                   \
        _Pragma("unroll")                                                     \
        for (int it = 0; it < 4; it++) {                                      \
            int idx = it * 128 + tid;                                         \
            int row = idx >> 2, ch = (idx & 3) * 8;                           \
            int arow = m0 + row;                                              \
            bool v = arow < M;                                                \
            int crow = v ? arow : (M - 1);                                    \
            size_t aoff = (size_t)crow * GK + k0i + ch;                       \
            size_t boff = (size_t)(n0 + row) * GK + k0i + ch;                 \
            cp16(dAh + row * SPITCH + ch, Ah + aoff, v);                      \
            cp16(dAl + row * SPITCH + ch, Al + aoff, v);                      \
            cp16(dBh + row * SPITCH + ch, Bh + boff, true);                   \
            cp16(dBl + row * SPITCH + ch, Bl + boff, true);                   \
        }                                                                     \
        asm volatile("cp.async.commit_group;");                               \
    }

    ISSUE_TILE(0, 0);

    for (int kt = 0; kt < NK; kt++) {
        const int buf = kt & 1;
        if (kt + 1 < NK) {
            ISSUE_TILE(kt + 1, buf ^ 1);
            asm volatile("cp.async.wait_group 1;");
        } else {
            asm volatile("cp.async.wait_group 0;");
        }
        __syncthreads();

        const __nv_bfloat16* cAh = smg + (buf * 4 + 0) * GTILE;
        const __nv_bfloat16* cAl = smg + (buf * 4 + 1) * GTILE;
        const __nv_bfloat16* cBh = smg + (buf * 4 + 2) * GTILE;
        const __nv_bfloat16* cBl = smg + (buf * 4 + 3) * GTILE;

#pragma unroll
        for (int ks = 0; ks < 2; ks++) {
            const int kb = ks * 16 + tq;
            unsigned ah[4][4], al[4][4];
#pragma unroll
            for (int mt = 0; mt < 4; mt++) {
                int r = wm + mt * 16 + quad;
                ah[mt][0] = *(const unsigned*)(cAh + r * SPITCH + kb);
                ah[mt][1] = *(const unsigned*)(cAh + (r + 8) * SPITCH + kb);
                ah[mt][2] = *(const unsigned*)(cAh + r * SPITCH + kb + 8);
                ah[mt][3] = *(const unsigned*)(cAh + (r + 8) * SPITCH + kb + 8);
                al[mt][0] = *(const unsigned*)(cAl + r * SPITCH + kb);
                al[mt][1] = *(const unsigned*)(cAl + (r + 8) * SPITCH + kb);
                al[mt][2] = *(const unsigned*)(cAl + r * SPITCH + kb + 8);
                al[mt][3] = *(const unsigned*)(cAl + (r + 8) * SPITCH + kb + 8);
            }
#pragma unroll
            for (int nt = 0; nt < 8; nt++) {
                int bn = wn + nt * 8 + quad;
                unsigned bh0 = *(const unsigned*)(cBh + bn * SPITCH + kb);
                unsigned bh1 = *(const unsigned*)(cBh + bn * SPITCH + kb + 8);
                unsigned bl0 = *(const unsigned*)(cBl + bn * SPITCH + kb);
                unsigned bl1 = *(const unsigned*)(cBl + bn * SPITCH + kb + 8);
#pragma unroll
                for (int mt = 0; mt < 4; mt++) {
                    mma_bf16(acc[mt][nt], ah[mt], bh0, bh1);
                    mma_bf16(acc[mt][nt], al[mt], bh0, bh1);
                    mma_bf16(acc[mt][nt], ah[mt], bl0, bl1);
                }
            }
        }
        __syncthreads();
    }

    // epilogue
#pragma unroll
    for (int mt = 0; mt < 4; mt++) {
        int r0 = m0 + wm + mt * 16 + quad;
#pragma unroll
        for (int nt = 0; nt < 8; nt++) {
            int col = n0 + wn + nt * 8 + tq;
            float b0 = bias[col], b1 = bias[col + 1];
            float v00 = acc[mt][nt][0] + b0, v01 = acc[mt][nt][1] + b1;
            float v10 = acc[mt][nt][2] + b0, v11 = acc[mt][nt][3] + b1;
            if (SPLIT_OUT) {
                unsigned h, l;
                if (r0 < M) {
                    split2(v00, v01, h, l);
                    *(unsigned*)(Ch + (size_t)r0 * GK + col) = h;
                    *(unsigned*)(Cl + (size_t)r0 * GK + col) = l;
                }
                if (r0 + 8 < M) {
                    split2(v10, v11, h, l);
                    *(unsigned*)(Ch + (size_t)(r0 + 8) * GK + col) = h;
                    *(unsigned*)(Cl + (size_t)(r0 + 8) * GK + col) = l;
                }
            } else {
                if (r0 < M)
                    *(float2*)(C + (size_t)r0 * GK + col) = make_float2(v00, v01);
                if (r0 + 8 < M)
                    *(float2*)(C + (size_t)(r0 + 8) * GK + col) = make_float2(v10, v11);
            }
        }
    }
}

// ---------------------------------------------------------------------------
// RMSNorm + 3D RoPE, fused with hi/lo split output.  One block per token.
// ---------------------------------------------------------------------------
__global__ void norm_rope_split_kernel(const float* __restrict__ data,
                                       const float* __restrict__ g,
                                       const float* __restrict__ freqs,
                                       __nv_bfloat16* __restrict__ oh,
                                       __nv_bfloat16* __restrict__ ol) {
    const int t = blockIdx.x;
    const int tid = threadIdx.x;
    const float* row = data + (size_t)t * DIM_;

    float ss = 0.f;
    for (int c = tid; c < DIM_; c += 256) { float v = row[c]; ss += v * v; }
#pragma unroll
    for (int o = 16; o; o >>= 1) ss += __shfl_xor_sync(0xffffffffu, ss, o);

    __shared__ float red[8];
    __shared__ float inv_s;
    if ((tid & 31) == 0) red[tid >> 5] = ss;
    __syncthreads();
    if (tid == 0) {
        float tot = 0.f;
#pragma unroll
        for (int i = 0; i < 8; i++) tot += red[i];
        inv_s = rsqrtf(tot / (float)DIM_ + 1e-6f);
    }
    __syncthreads();
    const float inv = inv_s;

    const int f = t / FRAME, rem = t % FRAME;
    const int hh = rem / WW, ww = rem % WW;

    for (int p = tid; p < DIM_ / 2; p += 256) {
        int pin = p & 63;
        int pos = (pin < 22) ? f : ((pin < 43) ? hh : ww);
        float cs = freqs[(pos * 64 + pin) * 2 + 0];
        float sn = freqs[(pos * 64 + pin) * 2 + 1];
        int c = p * 2;
        float a = row[c]     * inv * g[c];
        float b = row[c + 1] * inv * g[c + 1];
        float ra = a * cs - b * sn;
        float rb = a * sn + b * cs;
        unsigned h, l;
        split2(ra, rb, h, l);
        *(unsigned*)(oh + (size_t)t * DIM_ + c) = h;
        *(unsigned*)(ol + (size_t)t * DIM_ + c) = l;
    }
}

// ---------------------------------------------------------------------------
// Tensor-core flash attention, split-bf16 3-pass (verified R4), epilogue
// fused with hi/lo split output.
// ---------------------------------------------------------------------------
#define QP 136
#define VP 72

__global__ __launch_bounds__(256, 1)
void attn_mma_kernel(const __nv_bfloat16* __restrict__ Qh,
                     const __nv_bfloat16* __restrict__ Ql,
                     const __nv_bfloat16* __restrict__ Kh,
                     const __nv_bfloat16* __restrict__ Kl,
                     const __nv_bfloat16* __restrict__ Vh,
                     const __nv_bfloat16* __restrict__ Vl,
                     __nv_bfloat16* __restrict__ Oh,
                     __nv_bfloat16* __restrict__ Ol) {
    extern __shared__ __nv_bfloat16 smb[];
    __nv_bfloat16* sQh = smb;
    __nv_bfloat16* sQl = sQh + 128 * QP;
    __nv_bfloat16* sKh = sQl + 128 * QP;
    __nv_bfloat16* sKl = sKh + 64 * QP;
    __nv_bfloat16* sVh = sKl + 64 * QP;
    __nv_bfloat16* sVl = sVh + 128 * VP;

    const int tid = threadIdx.x;
    const int lane = tid & 31, wid = tid >> 5;
    const int g = lane >> 2, tq2 = (lane & 3) * 2;
    const int h = blockIdx.y;
    const int q0 = blockIdx.x * 128;
    const int r0 = wid * 16;
    const float scale = 0.08838834764831845f;

#pragma unroll
    for (int it = 0; it < 8; it++) {
        int idx = it * 256 + tid;
        int row = idx >> 4, ch = (idx & 15) * 8;
        uint4 zh = make_uint4(0, 0, 0, 0), zl = zh;
        if (q0 + row < L_TOK) {
            size_t off = (size_t)(q0 + row) * DIM_ + h * HD + ch;
            zh = *(const uint4*)(Qh + off);
            zl = *(const uint4*)(Ql + off);
        }
        *(uint4*)(sQh + row * QP + ch) = zh;
        *(uint4*)(sQl + row * QP + ch) = zl;
    }

    float m_pr0 = -INFINITY, m_pr1 = -INFINITY;
    float l0 = 0.f, l1 = 0.f;
    float oacc[16][4];
#pragma unroll
    for (int i = 0; i < 16; i++)
#pragma unroll
        for (int j = 0; j < 4; j++) oacc[i][j] = 0.f;

    const int row_g0 = q0 + r0 + g, row_g1 = row_g0 + 8;
    const int qf0 = min(row_g0, L_TOK - 1) / FRAME;
    const int qf1 = min(row_g1, L_TOK - 1) / FRAME;

    const int qmax = min(q0 + 127, L_TOK - 1);
    const int kend = min(L_TOK, (qmax / FRAME + 1) * FRAME);
    const int ntiles = (kend + 63) >> 6;

    for (int t = 0; t < ntiles; t++) {
        const int k0 = t * 64;
        __syncthreads();
#pragma unroll
        for (int it = 0; it < 4; it++) {
            int idx = it * 256 + tid;
            int row = idx >> 4, ch = (idx & 15) * 8;
            uint4 zh = make_uint4(0, 0, 0, 0), zl = zh;
            if (k0 + row < L_TOK) {
                size_t off = (size_t)(k0 + row) * DIM_ + h * HD + ch;
                zh = *(const uint4*)(Kh + off);
                zl = *(const uint4*)(Kl + off);
            }
            *(uint4*)(sKh + row * QP + ch) = zh;
            *(uint4*)(sKl + row * QP + ch) = zl;
        }
#pragma unroll
        for (int it = 0; it < 4; it++) {
            int idx = it * 256 + tid;
            int key = idx & 63, dc = (idx >> 6) * 8;
            uint4 zh = make_uint4(0, 0, 0, 0), zl = zh;
            if (k0 + key < L_TOK) {
                size_t off = (size_t)(k0 + key) * DIM_ + h * HD + dc;
                zh = *(const uint4*)(Vh + off);
                zl = *(const uint4*)(Vl + off);
            }
            const __nv_bfloat16* eh = reinterpret_cast<const __nv_bfloat16*>(&zh);
            const __nv_bfloat16* el = reinterpret_cast<const __nv_bfloat16*>(&zl);
#pragma unroll
            for (int e = 0; e < 8; e++) {
                sVh[(dc + e) * VP + key] = eh[e];
                sVl[(dc + e) * VP + key] = el[e];
            }
        }
        __syncthreads();

        float sacc[8][4];
#pragma unroll
        for (int i = 0; i < 8; i++)
#pragma unroll
            for (int j = 0; j < 4; j++) sacc[i][j] = 0.f;

#pragma unroll
        for (int kc = 0; kc < 8; kc++) {
            const int kb = kc * 16 + tq2;
            unsigned qh[4], ql[4];
            qh[0] = *(const unsigned*)(sQh + (r0 + g) * QP + kb);
            qh[1] = *(const unsigned*)(sQh + (r0 + g + 8) * QP + kb);
            qh[2] = *(const unsigned*)(sQh + (r0 + g) * QP + kb + 8);
            qh[3] = *(const unsigned*)(sQh + (r0 + g + 8) * QP + kb + 8);
            ql[0] = *(const unsigned*)(sQl + (r0 + g) * QP + kb);
            ql[1] = *(const unsigned*)(sQl + (r0 + g + 8) * QP + kb);
            ql[2] = *(const unsigned*)(sQl + (r0 + g) * QP + kb + 8);
            ql[3] = *(const unsigned*)(sQl + (r0 + g + 8) * QP + kb + 8);
#pragma unroll
            for (int nt = 0; nt < 8; nt++) {
                const int kr = nt * 8 + g;
                unsigned kh0 = *(const unsigned*)(sKh + kr * QP + kb);
                unsigned kh1 = *(const unsigned*)(sKh + kr * QP + kb + 8);
                unsigned kl0 = *(const unsigned*)(sKl + kr * QP + kb);
                unsigned kl1 = *(const unsigned*)(sKl + kr * QP + kb + 8);
                mma_bf16(sacc[nt], qh, kh0, kh1);
                mma_bf16(sacc[nt], ql, kh0, kh1);
                mma_bf16(sacc[nt], qh, kl0, kl1);
            }
        }

        float mloc0 = -INFINITY, mloc1 = -INFINITY;
#pragma unroll
        for (int nt = 0; nt < 8; nt++) {
            int c0 = k0 + nt * 8 + tq2, c1 = c0 + 1;
            int kf0 = c0 / FRAME, kf1 = c1 / FRAME;
            bool a00 = (c0 < L_TOK) && kf0 <= qf0 && (kf0 < SINK || qf0 - kf0 < LOCAL);
            bool a10 = (c1 < L_TOK) && kf1 <= qf0 && (kf1 < SINK || qf0 - kf1 < LOCAL);
            bool a01 = (c0 < L_TOK) && kf0 <= qf1 && (kf0 < SINK || qf1 - kf0 < LOCAL);
            bool a11 = (c1 < L_TOK) && kf1 <= qf1 && (kf1 < SINK || qf1 - kf1 < LOCAL);
            sacc[nt][0] = a00 ? sacc[nt][0] * scale : -INFINITY;
            sacc[nt][1] = a10 ? sacc[nt][1] * scale : -INFINITY;
            sacc[nt][2] = a01 ? sacc[nt][2] * scale : -INFINITY;
            sacc[nt][3] = a11 ? sacc[nt][3] * scale : -INFINITY;
            mloc0 = fmaxf(mloc0, fmaxf(sacc[nt][0], sacc[nt][1]));
            mloc1 = fmaxf(mloc1, fmaxf(sacc[nt][2], sacc[nt][3]));
        }
        mloc0 = fmaxf(mloc0, __shfl_xor_sync(0xffffffffu, mloc0, 1));
        mloc0 = fmaxf(mloc0, __shfl_xor_sync(0xffffffffu, mloc0, 2));
        mloc1 = fmaxf(mloc1, __shfl_xor_sync(0xffffffffu, mloc1, 1));
        mloc1 = fmaxf(mloc1, __shfl_xor_sync(0xffffffffu, mloc1, 2));

        float mn0 = fmaxf(m_pr0, mloc0), mn1 = fmaxf(m_pr1, mloc1);
        float alpha0 = __expf(m_pr0 - mn0), alpha1 = __expf(m_pr1 - mn1);
        m_pr0 = mn0; m_pr1 = mn1;

        float rs0 = 0.f, rs1 = 0.f;
#pragma unroll
        for (int nt = 0; nt < 8; nt++) {
            sacc[nt][0] = __expf(sacc[nt][0] - mn0);
            sacc[nt][1] = __expf(sacc[nt][1] - mn0);
            sacc[nt][2] = __expf(sacc[nt][2] - mn1);
            sacc[nt][3] = __expf(sacc[nt][3] - mn1);
            rs0 += sacc[nt][0] + sacc[nt][1];
            rs1 += sacc[nt][2] + sacc[nt][3];
        }
        rs0 += __shfl_xor_sync(0xffffffffu, rs0, 1);
        rs0 += __shfl_xor_sync(0xffffffffu, rs0, 2);
        rs1 += __shfl_xor_sync(0xffffffffu, rs1, 1);
        rs1 += __shfl_xor_sync(0xffffffffu, rs1, 2);
        l0 = l0 * alpha0 + rs0;
        l1 = l1 * alpha1 + rs1;

#pragma unroll
        for (int dt = 0; dt < 16; dt++) {
            oacc[dt][0] *= alpha0; oacc[dt][1] *= alpha0;
            oacc[dt][2] *= alpha1; oacc[dt][3] *= alpha1;
        }

#pragma unroll
        for (int kc2 = 0; kc2 < 4; kc2++) {
            unsigned pah[4], pal[4];
            split2(sacc[2 * kc2][0],     sacc[2 * kc2][1],     pah[0], pal[0]);
            split2(sacc[2 * kc2][2],     sacc[2 * kc2][3],     pah[1], pal[1]);
            split2(sacc[2 * kc2 + 1][0], sacc[2 * kc2 + 1][1], pah[2], pal[2]);
            split2(sacc[2 * kc2 + 1][2], sacc[2 * kc2 + 1][3], pah[3], pal[3]);
            const int kb2 = kc2 * 16 + tq2;
#pragma unroll
            for (int dt = 0; dt < 16; dt++) {
                const int vr = dt * 8 + g;
                unsigned vh0 = *(const unsigned*)(sVh + vr * VP + kb2);
                unsigned vh1 = *(const unsigned*)(sVh + vr * VP + kb2 + 8);
                unsigned vl0 = *(const unsigned*)(sVl + vr * VP + kb2);
                unsigned vl1 = *(const unsigned*)(sVl + vr * VP + kb2 + 8);
                mma_bf16(oacc[dt], pah, vh0, vh1);
                mma_bf16(oacc[dt], pal, vh0, vh1);
                mma_bf16(oacc[dt], pah, vl0, vl1);
            }
        }
    }

    // epilogue: normalize + split to hi/lo planes directly
    const float li0 = 1.f / l0, li1 = 1.f / l1;
#pragma unroll
    for (int dt = 0; dt < 16; dt++) {
        const int d = dt * 8 + tq2;
        unsigned sh, sl;
        if (row_g0 < L_TOK) {
            split2(oacc[dt][0] * li0, oacc[dt][1] * li0, sh, sl);
            *(unsigned*)(Oh + (size_t)row_g0 * DIM_ + h * HD + d) = sh;
            *(unsigned*)(Ol + (size_t)row_g0 * DIM_ + h * HD + d) = sl;
        }
        if (row_g1 < L_TOK) {
            split2(oacc[dt][2] * li1, oacc[dt][3] * li1, sh, sl);
            *(unsigned*)(Oh + (size_t)row_g1 * DIM_ + h * HD + d) = sh;
            *(unsigned*)(Ol + (size_t)row_g1 * DIM_ + h * HD + d) = sl;
        }
    }
}

// ---------------------------------------------------------------------------
extern "C" void kernel_launch(void* const* d_in, const int* in_sizes, int n_in,
                              void* d_out, int out_size) {
    const float* x  = (const float*)d_in[0];
    const float* wq = (const float*)d_in[1];
    const float* bq = (const float*)d_in[2];
    const float* wk = (const float*)d_in[3];
    const float* bk = (const float*)d_in[4];
    const float* wv = (const float*)d_in[5];
    const float* bv = (const float*)d_in[6];
    const float* wo = (const float*)d_in[7];
    const float* bo = (const float*)d_in[8];
    const float* gq = (const float*)d_in[9];
    const float* gk = (const float*)d_in[10];
    const float* fr = (const float*)d_in[11];
    float* out = (float*)d_out;

    float *q, *k;
    __nv_bfloat16 *ah, *al, *qwh, *qwl, *kwh, *kwl, *vwh, *vwl, *owh, *owl;
    __nv_bfloat16 *qh, *ql, *kh, *kl, *vh, *vl;
    cudaGetSymbolAddress((void**)&q, g_q);
    cudaGetSymbolAddress((void**)&k, g_k);
    cudaGetSymbolAddress((void**)&ah, g_act_hi);
    cudaGetSymbolAddress((void**)&al, g_act_lo);
    cudaGetSymbolAddress((void**)&qwh, g_wq_hi);
    cudaGetSymbolAddress((void**)&qwl, g_wq_lo);
    cudaGetSymbolAddress((void**)&kwh, g_wk_hi);
    cudaGetSymbolAddress((void**)&kwl, g_wk_lo);
    cudaGetSymbolAddress((void**)&vwh, g_wv_hi);
    cudaGetSymbolAddress((void**)&vwl, g_wv_lo);
    cudaGetSymbolAddress((void**)&owh, g_wo_hi);
    cudaGetSymbolAddress((void**)&owl, g_wo_lo);
    cudaGetSymbolAddress((void**)&qh, g_qh);
    cudaGetSymbolAddress((void**)&ql, g_ql);
    cudaGetSymbolAddress((void**)&kh, g_kh);
    cudaGetSymbolAddress((void**)&kl, g_kl);
    cudaGetSymbolAddress((void**)&vh, g_vh);
    cudaGetSymbolAddress((void**)&vl, g_vl);

    const int nact4 = L_TOK * DIM_ / 4;
    const int nw4 = DIM_ * DIM_ / 4;
    const int SB = 256;
    dim3 gact((nact4 + SB - 1) / SB), gw((nw4 + SB - 1) / SB);
    dim3 gg(DIM_ / 128, (L_TOK + 127) / 128);

    const int gsmem = 2 * 4 * GTILE * (int)sizeof(__nv_bfloat16);  // 81920
    cudaFuncSetAttribute(gemm_bf16s_v2<false>,
                         cudaFuncAttributeMaxDynamicSharedMemorySize, gsmem);
    cudaFuncSetAttribute(gemm_bf16s_v2<true>,
                         cudaFuncAttributeMaxDynamicSharedMemorySize, gsmem);

    // input splits
    split_kernel<<<gact, SB>>>((const float4*)x, (__nv_bfloat162*)ah,
                               (__nv_bfloat162*)al, nact4);
    split_kernel<<<gw, SB>>>((const float4*)wq, (__nv_bfloat162*)qwh,
                             (__nv_bfloat162*)qwl, nw4);
    split_kernel<<<gw, SB>>>((const float4*)wk, (__nv_bfloat162*)kwh,
                             (__nv_bfloat162*)kwl, nw4);
    split_kernel<<<gw, SB>>>((const float4*)wv, (__nv_bfloat162*)vwh,
                             (__nv_bfloat162*)vwl, nw4);
    split_kernel<<<gw, SB>>>((const float4*)wo, (__nv_bfloat162*)owh,
                             (__nv_bfloat162*)owl, nw4);

    // projections: q,k -> fp32 (need norm); v -> hi/lo planes directly
    gemm_bf16s_v2<false><<<gg, 128, gsmem>>>(ah, al, qwh, qwl, bq, q,
                                             nullptr, nullptr, L_TOK);
    gemm_bf16s_v2<false><<<gg, 128, gsmem>>>(ah, al, kwh, kwl, bk, k,
                                             nullptr, nullptr, L_TOK);
    gemm_bf16s_v2<true><<<gg, 128, gsmem>>>(ah, al, vwh, vwl, bv, nullptr,
                                            vh, vl, L_TOK);

    // fused norm + rope + split
    norm_rope_split_kernel<<<L_TOK, 256>>>(q, gq, fr, qh, ql);
    norm_rope_split_kernel<<<L_TOK, 256>>>(k, gk, fr, kh, kl);

    // attention writes its output hi/lo planes into the act buffers
    // (x-split planes are fully consumed by the three projection GEMMs above)
    size_t asmem = (size_t)(2 * 128 * QP + 2 * 64 * QP + 2 * 128 * VP) *
                   sizeof(__nv_bfloat16);
    cudaFuncSetAttribute(attn_mma_kernel,
                         cudaFuncAttributeMaxDynamicSharedMemorySize, (int)asmem);
    attn_mma_kernel<<<dim3((L_TOK + 127) / 128, NH), 256, asmem>>>(
        qh, ql, kh, kl, vh, vl, ah, al);

    // output projection
    gemm_bf16s_v2<false><<<gg, 128, gsmem>>>(ah, al, owh, owl, bo, out,
                                             nullptr, nullptr, L_TOK);
}